// round 8
// baseline (speedup 1.0000x reference)
#include <cuda_runtime.h>
#include <cuda_bf16.h>
#include <cstdint>

#define NN 100000
#define NE 800000
#define HD 256
#define KE 259      // H + 3 edge features
#define NL 6

// ---------------- scratch (static device globals) ----------------
static __device__ __align__(16) __nv_bfloat16 g_ahi[(size_t)NN * HD];
static __device__ __align__(16) __nv_bfloat16 g_alo[(size_t)NN * HD];
static __device__ __align__(16) __nv_bfloat16 g_bhi[(size_t)NN * HD];
static __device__ __align__(16) __nv_bfloat16 g_blo[(size_t)NN * HD];
static __device__ __align__(16) __nv_bfloat16 g_nhi[(size_t)NN * HD];
static __device__ __align__(16) __nv_bfloat16 g_nlo[(size_t)NN * HD];
static __device__ float g_z[(size_t)NN * HD];
#define W1SZ (NL * HD * HD)
#define W2SZ (NL * HD * 512)
#define WHSZ (HD * HD)
static __device__ __align__(16) __nv_bfloat16 g_w1hi[W1SZ], g_w1lo[W1SZ];
static __device__ __align__(16) __nv_bfloat16 g_w2hi[W2SZ], g_w2lo[W2SZ];
static __device__ __align__(16) __nv_bfloat16 g_whhi[WHSZ], g_whlo[WHSZ];

static __device__ float g_inv[NN];
static __device__ int   g_deg[NN];
static __device__ int   g_rowptr[NN + 1];
static __device__ int   g_cursor[NN];
static __device__ int   g_esorted[NE];

// ---------------- preprocessing: deterministic CSR by dst ----------------
__global__ void k_deg(const int* __restrict__ dst, int e) {
    int i = blockIdx.x * blockDim.x + threadIdx.x;
    if (i < e) atomicAdd(&g_deg[dst[i]], 1);
}

__global__ void k_scan(int n) {
    __shared__ int s[1024];
    int t = threadIdx.x;
    int per = (n + 1023) / 1024;
    int lo = t * per;
    int hi = lo + per; if (hi > n) hi = n;
    int sum = 0;
    for (int i = lo; i < hi; i++) sum += g_deg[i];
    s[t] = sum;
    __syncthreads();
    for (int off = 1; off < 1024; off <<= 1) {
        int v = (t >= off) ? s[t - off] : 0;
        __syncthreads();
        s[t] += v;
        __syncthreads();
    }
    int run = s[t] - sum;
    for (int i = lo; i < hi; i++) {
        g_rowptr[i] = run;
        g_cursor[i] = run;
        g_inv[i] = 1.0f / fmaxf((float)g_deg[i], 1.0f);
        run += g_deg[i];
    }
    if (t == 1023) g_rowptr[n] = s[1023];
}

__global__ void k_scatter(const int* __restrict__ dst, int e) {
    int i = blockIdx.x * blockDim.x + threadIdx.x;
    if (i < e) {
        int d = dst[i];
        int pos = atomicAdd(&g_cursor[d], 1);
        g_esorted[pos] = i;
    }
}

__global__ void k_segsort(int n) {
    int v = blockIdx.x * blockDim.x + threadIdx.x;
    if (v >= n) return;
    int lo = g_rowptr[v], hi = g_rowptr[v + 1];
    for (int i = lo + 1; i < hi; i++) {
        int key = g_esorted[i];
        int j = i - 1;
        while (j >= lo && g_esorted[j] > key) { g_esorted[j + 1] = g_esorted[j]; j--; }
        g_esorted[j + 1] = key;
    }
}

// ---------------- weight pre-split ----------------
__global__ void k_wsplit(const float* __restrict__ W1, const float* __restrict__ W2,
                         const float* __restrict__ Wh1) {
    int i = blockIdx.x * blockDim.x + threadIdx.x;
    float v; __nv_bfloat16* dh; __nv_bfloat16* dl; int o;
    if (i < W1SZ) {
        int l = i / (HD * HD), rem = i % (HD * HD);
        int row = rem / HD, col = rem % HD;
        v = W1[(size_t)l * HD * KE + (size_t)row * KE + col];
        dh = g_w1hi; dl = g_w1lo; o = i;
    } else if (i < W1SZ + W2SZ) {
        o = i - W1SZ;
        v = W2[o];
        dh = g_w2hi; dl = g_w2lo;
    } else if (i < W1SZ + W2SZ + WHSZ) {
        o = i - W1SZ - W2SZ;
        v = Wh1[o];
        dh = g_whhi; dl = g_whlo;
    } else return;
    __nv_bfloat16 h = __float2bfloat16_rn(v);
    dh[o] = h;
    dl[o] = __float2bfloat16_rn(v - __bfloat162float(h));
}

// ---------------- init (h only; inv handled in k_scan) ----------------
__global__ void k_init(const int* __restrict__ gate, const float* __restrict__ emb, int n) {
    int idx = blockIdx.x * blockDim.x + threadIdx.x;
    if (idx >= n * HD) return;
    int v = idx / HD, f = idx % HD;
    float x = emb[gate[v] * HD + f];
    __nv_bfloat16 h = __float2bfloat16_rn(x);
    g_ahi[idx] = h;
    g_alo[idx] = __float2bfloat16_rn(x - __bfloat162float(h));
}

// ---------------- warp-MMA helpers ----------------
__device__ __forceinline__ uint32_t s2u(const void* p) {
    return (uint32_t)__cvta_generic_to_shared(p);
}
__device__ __forceinline__ void ldsm4(uint32_t* r, uint32_t addr) {
    asm volatile("ldmatrix.sync.aligned.m8n8.x4.shared.b16 {%0,%1,%2,%3}, [%4];"
        : "=r"(r[0]), "=r"(r[1]), "=r"(r[2]), "=r"(r[3]) : "r"(addr));
}
__device__ __forceinline__ void mma16816(float* d, const uint32_t* a, const uint32_t* b) {
    asm volatile("mma.sync.aligned.m16n8k16.row.col.f32.bf16.bf16.f32 "
        "{%0,%1,%2,%3}, {%4,%5,%6,%7}, {%8,%9}, {%0,%1,%2,%3};"
        : "+f"(d[0]), "+f"(d[1]), "+f"(d[2]), "+f"(d[3])
        : "r"(a[0]), "r"(a[1]), "r"(a[2]), "r"(a[3]), "r"(b[0]), "r"(b[1]));
}
__device__ __forceinline__ void cpa16(uint32_t d, const void* s) {
    asm volatile("cp.async.ca.shared.global [%0], [%1], 16;" :: "r"(d), "l"(s));
}
#define CP_COMMIT() asm volatile("cp.async.commit_group;" ::: "memory")

// ---------------- bf16x3 MMA GEMM, 512 threads, cp.async double-buffered ----------------
// 16 warps, warp grid 4(m) x 4(n), warp tile 32x32 (mf=2, nf=4).
// MMA schedule: 3 passes (hh, lh, hl) across all 8 warp tiles -> per-acc order
// unchanged (bit-identical) but same-acc RAW chains spaced 8 apart.
#define PITCH 40
#define STG   40960
__global__ __launch_bounds__(512) void k_gemm_mma(
    const __nv_bfloat16* __restrict__ A0h, const __nv_bfloat16* __restrict__ A0l,
    const __nv_bfloat16* __restrict__ A1h, const __nv_bfloat16* __restrict__ A1l,
    const __nv_bfloat16* __restrict__ Bh,  const __nv_bfloat16* __restrict__ Bl,
    const float* __restrict__ bias,
    float* __restrict__ outf, __nv_bfloat16* __restrict__ outhi, __nv_bfloat16* __restrict__ outlo,
    int K, int ws, int M, int act)
{
    extern __shared__ char smem[];
    const uint32_t us = s2u(smem);

    const int tid  = threadIdx.x;
    const int lane = tid & 31;
    const int wid  = tid >> 5;
    const int r0   = blockIdx.x * 128;
    const int nb0  = blockIdx.y * 128;
    const int m0w  = (wid >> 2) * 32;
    const int n0w  = (wid & 3) * 32;

    float acc[2][4][4];
#pragma unroll
    for (int i = 0; i < 2; i++)
#pragma unroll
        for (int j = 0; j < 4; j++)
#pragma unroll
            for (int t = 0; t < 4; t++) acc[i][j][t] = 0.f;

    const int nch = K >> 5;
    const int lr  = tid >> 2;
    const int lc8 = (tid & 3) * 8;

    auto load_chunk = [&](int ch, int stage) {
        const int kc = ch << 5;
        const __nv_bfloat16* Ah = (kc < HD) ? A0h : A1h;
        const __nv_bfloat16* Al = (kc < HD) ? A0l : A1l;
        const int acol = (kc < HD) ? kc : (kc - HD);
        const uint32_t base = us + stage * STG;
        int g = r0 + lr; if (g >= M) g = M - 1;
        uint32_t so = (uint32_t)(lr * PITCH + lc8) * 2;
        cpa16(base + so,         &Ah[(size_t)g * HD + acol + lc8]);
        cpa16(base + 10240 + so, &Al[(size_t)g * HD + acol + lc8]);
        cpa16(base + 20480 + so, &Bh[(size_t)(nb0 + lr) * ws + kc + lc8]);
        cpa16(base + 30720 + so, &Bl[(size_t)(nb0 + lr) * ws + kc + lc8]);
    };

    load_chunk(0, 0);
    CP_COMMIT();

    for (int ch = 0; ch < nch; ch++) {
        if (ch + 1 < nch) {
            load_chunk(ch + 1, (ch + 1) & 1);
            CP_COMMIT();
            asm volatile("cp.async.wait_group 1;" ::: "memory");
        } else {
            asm volatile("cp.async.wait_group 0;" ::: "memory");
        }
        __syncthreads();

        const uint32_t base = us + (ch & 1) * STG;
        const uint32_t uA = base, uAl = base + 10240, uB = base + 20480, uBl = base + 30720;
#pragma unroll
        for (int ks = 0; ks < 2; ks++) {
            const int kk = ks * 16;
            uint32_t ah[2][4], al[2][4];
            {
                int ar = (lane & 7) + ((lane >> 3) & 1) * 8;
                int ac = kk + ((lane >> 4) & 1) * 8;
#pragma unroll
                for (int mf = 0; mf < 2; mf++) {
                    uint32_t off = (uint32_t)((m0w + mf * 16 + ar) * PITCH + ac) * 2;
                    ldsm4(ah[mf], uA + off);
                    ldsm4(al[mf], uAl + off);
                }
            }
            uint32_t bh[2][4], bl[2][4];
            {
                int br = ((lane >> 4) & 1) * 8 + (lane & 7);
                int bc = kk + ((lane >> 3) & 1) * 8;
#pragma unroll
                for (int nb2 = 0; nb2 < 2; nb2++) {
                    uint32_t off = (uint32_t)((n0w + nb2 * 16 + br) * PITCH + bc) * 2;
                    ldsm4(bh[nb2], uB + off);
                    ldsm4(bl[nb2], uBl + off);
                }
            }
            // pass 1: hh
#pragma unroll
            for (int mf = 0; mf < 2; mf++)
#pragma unroll
                for (int nf = 0; nf < 4; nf++)
                    mma16816(acc[mf][nf], ah[mf], &bh[nf >> 1][(nf & 1) * 2]);
            // pass 2: lh
#pragma unroll
            for (int mf = 0; mf < 2; mf++)
#pragma unroll
                for (int nf = 0; nf < 4; nf++)
                    mma16816(acc[mf][nf], al[mf], &bh[nf >> 1][(nf & 1) * 2]);
            // pass 3: hl
#pragma unroll
            for (int mf = 0; mf < 2; mf++)
#pragma unroll
                for (int nf = 0; nf < 4; nf++)
                    mma16816(acc[mf][nf], ah[mf], &bl[nf >> 1][(nf & 1) * 2]);
        }
        __syncthreads();
    }

    // epilogue
    const int rq = lane >> 2, cq = (lane & 3) * 2;
#pragma unroll
    for (int mf = 0; mf < 2; mf++) {
#pragma unroll
        for (int nf = 0; nf < 4; nf++) {
            int col = nb0 + n0w + nf * 8 + cq;
            float b0 = 0.f, b1 = 0.f;
            if (bias) { b0 = __ldg(&bias[col]); b1 = __ldg(&bias[col + 1]); }
            int row0 = r0 + m0w + mf * 16 + rq;
#pragma unroll
            for (int half = 0; half < 2; half++) {
                int row = row0 + half * 8;
                if (row < M) {
                    float ox = acc[mf][nf][half * 2 + 0] + b0;
                    float oy = acc[mf][nf][half * 2 + 1] + b1;
                    if (act) { ox = fmaxf(ox, 0.f); oy = fmaxf(oy, 0.f); }
                    size_t idx = (size_t)row * HD + col;
                    if (outf) *(float2*)&outf[idx] = make_float2(ox, oy);
                    if (outhi) {
                        __nv_bfloat16 h0 = __float2bfloat16_rn(ox);
                        __nv_bfloat16 h1 = __float2bfloat16_rn(oy);
                        *(__nv_bfloat162*)&outhi[idx] = {h0, h1};
                        *(__nv_bfloat162*)&outlo[idx] =
                            {__float2bfloat16_rn(ox - __bfloat162float(h0)),
                             __float2bfloat16_rn(oy - __bfloat162float(h1))};
                    }
                }
            }
        }
    }
}

// ---------------- fused edge + segmented mean: warp-per-node ----------------
#define ESEG_BLOCKS 1563
__global__ __launch_bounds__(256) void k_edge_seg(
    const float* __restrict__ z, const int* __restrict__ src,
    const float* __restrict__ w, const float* __restrict__ W1l, int n)
{
    __shared__ float sc[3][HD];
    const int tid  = threadIdx.x;
    const int lane = tid & 31;
    const int wloc = tid >> 5;

    if (tid < HD) {
        sc[0][tid] = W1l[(size_t)tid * KE + HD + 0];
        sc[1][tid] = W1l[(size_t)tid * KE + HD + 1];
        sc[2][tid] = W1l[(size_t)tid * KE + HD + 2];
    }
    __syncthreads();

    const int f0 = lane * 8;
    float c0[8], c1[8], c2[8];
#pragma unroll
    for (int j = 0; j < 8; j++) {
        c0[j] = sc[0][f0 + j];
        c1[j] = sc[1][f0 + j];
        c2[j] = sc[2][f0 + j];
    }

    const int gwarp  = blockIdx.x * 8 + wloc;
    const int nwarps = ESEG_BLOCKS * 8;

    for (int v = gwarp; v < n; v += nwarps) {
        const int lo = g_rowptr[v], hi = g_rowptr[v + 1];
        float a[8];
#pragma unroll
        for (int j = 0; j < 8; j++) a[j] = 0.f;

        for (int i = lo; i < hi; i++) {
            int e = __ldg(&g_esorted[i]);
            int s = __ldg(&src[e]);
            float w0 = __ldg(&w[(size_t)e * 3 + 0]);
            float w1 = __ldg(&w[(size_t)e * 3 + 1]);
            float w2 = __ldg(&w[(size_t)e * 3 + 2]);
            const float4* zr = (const float4*)&z[(size_t)s * HD];
            float4 za = __ldg(&zr[lane * 2 + 0]);
            float4 zb = __ldg(&zr[lane * 2 + 1]);
            float t[8];
            t[0] = za.x; t[1] = za.y; t[2] = za.z; t[3] = za.w;
            t[4] = zb.x; t[5] = zb.y; t[6] = zb.z; t[7] = zb.w;
#pragma unroll
            for (int j = 0; j < 8; j++) {
                float val = t[j] + c0[j] * w0 + c1[j] * w1 + c2[j] * w2;
                a[j] += (val > 0.f) ? val : 0.01f * val;
            }
        }
        const float inv = g_inv[v];
        uint32_t hpack[4], lpack[4];
#pragma unroll
        for (int j = 0; j < 4; j++) {
            float r0v = a[j * 2 + 0] * inv;
            float r1v = a[j * 2 + 1] * inv;
            __nv_bfloat16 h0 = __float2bfloat16_rn(r0v);
            __nv_bfloat16 h1 = __float2bfloat16_rn(r1v);
            __nv_bfloat162 hp = {h0, h1};
            __nv_bfloat162 lp = {__float2bfloat16_rn(r0v - __bfloat162float(h0)),
                                 __float2bfloat16_rn(r1v - __bfloat162float(h1))};
            hpack[j] = *(uint32_t*)&hp;
            lpack[j] = *(uint32_t*)&lp;
        }
        size_t idx = (size_t)v * HD + f0;
        *(uint4*)&g_nhi[idx] = *(uint4*)hpack;
        *(uint4*)&g_nlo[idx] = *(uint4*)lpack;
    }
}

// ---------------- head ----------------
__global__ void k_head2(const float* __restrict__ x, const float* __restrict__ Wh2,
                        const float* __restrict__ bh2, float* __restrict__ out, int n) {
    int gtid = blockIdx.x * blockDim.x + threadIdx.x;
    int v = gtid >> 5;
    int lane = gtid & 31;
    if (v >= n) return;
    float s = 0.f;
#pragma unroll
    for (int k = lane; k < HD; k += 32) s += x[(size_t)v * HD + k] * Wh2[k];
#pragma unroll
    for (int o = 16; o; o >>= 1) s += __shfl_xor_sync(0xffffffffu, s, o);
    if (lane == 0) out[v] = s + bh2[0];
}

// ---------------- host ----------------
extern "C" void kernel_launch(void* const* d_in, const int* in_sizes, int n_in,
                              void* d_out, int out_size) {
    const int*   gate = (const int*)  d_in[0];
    const int*   src  = (const int*)  d_in[1];
    const int*   dst  = (const int*)  d_in[2];
    const float* w    = (const float*)d_in[3];
    const float* emb  = (const float*)d_in[4];
    const float* W1   = (const float*)d_in[5];
    const float* W2   = (const float*)d_in[6];
    const float* b2   = (const float*)d_in[7];
    const float* Wh1  = (const float*)d_in[8];
    const float* bh1  = (const float*)d_in[9];
    const float* Wh2  = (const float*)d_in[10];
    const float* bh2  = (const float*)d_in[11];
    float* out = (float*)d_out;

    int n = in_sizes[0];
    int e = in_sizes[1];

    static int smem_set = 0;
    if (!smem_set) {
        cudaFuncSetAttribute(k_gemm_mma, cudaFuncAttributeMaxDynamicSharedMemorySize, 2 * STG);
        smem_set = 1;
    }

    void* p;
    cudaGetSymbolAddress(&p, g_ahi); __nv_bfloat16* ahi = (__nv_bfloat16*)p;
    cudaGetSymbolAddress(&p, g_alo); __nv_bfloat16* alo = (__nv_bfloat16*)p;
    cudaGetSymbolAddress(&p, g_bhi); __nv_bfloat16* bhi = (__nv_bfloat16*)p;
    cudaGetSymbolAddress(&p, g_blo); __nv_bfloat16* blo = (__nv_bfloat16*)p;
    cudaGetSymbolAddress(&p, g_nhi); __nv_bfloat16* nhi = (__nv_bfloat16*)p;
    cudaGetSymbolAddress(&p, g_nlo); __nv_bfloat16* nlo = (__nv_bfloat16*)p;
    cudaGetSymbolAddress(&p, g_z);   float* z = (float*)p;
    cudaGetSymbolAddress(&p, g_w1hi); __nv_bfloat16* w1hi = (__nv_bfloat16*)p;
    cudaGetSymbolAddress(&p, g_w1lo); __nv_bfloat16* w1lo = (__nv_bfloat16*)p;
    cudaGetSymbolAddress(&p, g_w2hi); __nv_bfloat16* w2hi = (__nv_bfloat16*)p;
    cudaGetSymbolAddress(&p, g_w2lo); __nv_bfloat16* w2lo = (__nv_bfloat16*)p;
    cudaGetSymbolAddress(&p, g_whhi); __nv_bfloat16* whhi = (__nv_bfloat16*)p;
    cudaGetSymbolAddress(&p, g_whlo); __nv_bfloat16* whlo = (__nv_bfloat16*)p;
    cudaGetSymbolAddress(&p, g_deg); int* degp = (int*)p;

    __nv_bfloat16 *pah = ahi, *pal = alo, *pbh = bhi, *pbl = blo;
    dim3 gg((n + 127) / 128, 2);

    // prep ordered so the layer-0 z-GEMM is the 6th launch (ncu -s 5 -c 1 captures it)
    cudaMemsetAsync(degp, 0, (size_t)n * sizeof(int));
    k_deg    <<<(e + 255) / 256, 256>>>(dst, e);
    k_scan   <<<1, 1024>>>(n);
    k_wsplit <<<(W1SZ + W2SZ + WHSZ + 255) / 256, 256>>>(W1, W2, Wh1);
    k_init   <<<((size_t)n * HD + 255) / 256, 256>>>(gate, emb, n);

    // layer 0 z-GEMM (depends only on init + wsplit)
    k_gemm_mma<<<gg, 512, 2 * STG>>>(pah, pal, pah, pal, w1hi, w1lo,
                                     nullptr, z, nullptr, nullptr, HD, HD, n, 0);
    // finish CSR (needed by edge_seg)
    k_scatter<<<(e + 255) / 256, 256>>>(dst, e);
    k_segsort<<<(n + 255) / 256, 256>>>(n);

    for (int l = 0; l < NL; l++) {
        const float* W1l = W1 + (size_t)l * HD * KE;
        if (l > 0) {
            k_gemm_mma<<<gg, 512, 2 * STG>>>(pah, pal, pah, pal,
                                             w1hi + (size_t)l * HD * HD, w1lo + (size_t)l * HD * HD,
                                             nullptr, z, nullptr, nullptr, HD, HD, n, 0);
        }
        k_edge_seg<<<ESEG_BLOCKS, 256>>>(z, src, w, W1l, n);
        k_gemm_mma<<<gg, 512, 2 * STG>>>(pah, pal, nhi, nlo,
                                         w2hi + (size_t)l * HD * 512, w2lo + (size_t)l * HD * 512,
                                         b2 + (size_t)l * HD, nullptr, pbh, pbl, 512, 512, n, 1);
        __nv_bfloat16* t;
        t = pah; pah = pbh; pbh = t;
        t = pal; pal = pbl; pbl = t;
    }
    k_gemm_mma<<<gg, 512, 2 * STG>>>(pah, pal, pah, pal, whhi, whlo,
                                     bh1, z, nullptr, nullptr, HD, HD, n, 1);
    k_head2<<<((size_t)n * 32 + 255) / 256, 256>>>(z, Wh2, bh2, out, n);
}

// round 9
// speedup vs baseline: 1.0647x; 1.0647x over previous
#include <cuda_runtime.h>
#include <cuda_bf16.h>
#include <cstdint>

#define NN 100000
#define NE 800000
#define HD 256
#define KE 259      // H + 3 edge features
#define NL 6

// ---------------- scratch (static device globals) ----------------
static __device__ __align__(16) __nv_bfloat16 g_ahi[(size_t)NN * HD];
static __device__ __align__(16) __nv_bfloat16 g_alo[(size_t)NN * HD];
static __device__ __align__(16) __nv_bfloat16 g_bhi[(size_t)NN * HD];
static __device__ __align__(16) __nv_bfloat16 g_blo[(size_t)NN * HD];
static __device__ __align__(16) __nv_bfloat16 g_nhi[(size_t)NN * HD];
static __device__ __align__(16) __nv_bfloat16 g_nlo[(size_t)NN * HD];
static __device__ float g_z[(size_t)NN * HD];
#define W1SZ (NL * HD * HD)
#define W2SZ (NL * HD * 512)
#define WHSZ (HD * HD)
static __device__ __align__(16) __nv_bfloat16 g_w1hi[W1SZ], g_w1lo[W1SZ];
static __device__ __align__(16) __nv_bfloat16 g_w2hi[W2SZ], g_w2lo[W2SZ];
static __device__ __align__(16) __nv_bfloat16 g_whhi[WHSZ], g_whlo[WHSZ];

static __device__ float g_inv[NN];
static __device__ int   g_deg[NN];
static __device__ int   g_rowptr[NN + 1];
static __device__ int   g_cursor[NN];
static __device__ int   g_esorted[NE];

// ---------------- preprocessing: deterministic CSR by dst ----------------
__global__ void k_deg(const int* __restrict__ dst, int e) {
    int i = blockIdx.x * blockDim.x + threadIdx.x;
    if (i < e) atomicAdd(&g_deg[dst[i]], 1);
}

__global__ void k_scan(int n) {
    __shared__ int s[1024];
    int t = threadIdx.x;
    int per = (n + 1023) / 1024;
    int lo = t * per;
    int hi = lo + per; if (hi > n) hi = n;
    int sum = 0;
    for (int i = lo; i < hi; i++) sum += g_deg[i];
    s[t] = sum;
    __syncthreads();
    for (int off = 1; off < 1024; off <<= 1) {
        int v = (t >= off) ? s[t - off] : 0;
        __syncthreads();
        s[t] += v;
        __syncthreads();
    }
    int run = s[t] - sum;
    for (int i = lo; i < hi; i++) {
        g_rowptr[i] = run;
        g_cursor[i] = run;
        run += g_deg[i];
    }
    if (t == 1023) g_rowptr[n] = s[1023];
}

__global__ void k_scatter(const int* __restrict__ dst, int e) {
    int i = blockIdx.x * blockDim.x + threadIdx.x;
    if (i < e) {
        int d = dst[i];
        int pos = atomicAdd(&g_cursor[d], 1);
        g_esorted[pos] = i;
    }
}

__global__ void k_segsort(int n) {
    int v = blockIdx.x * blockDim.x + threadIdx.x;
    if (v >= n) return;
    int lo = g_rowptr[v], hi = g_rowptr[v + 1];
    for (int i = lo + 1; i < hi; i++) {
        int key = g_esorted[i];
        int j = i - 1;
        while (j >= lo && g_esorted[j] > key) { g_esorted[j + 1] = g_esorted[j]; j--; }
        g_esorted[j + 1] = key;
    }
}

// ---------------- weight pre-split ----------------
__global__ void k_wsplit(const float* __restrict__ W1, const float* __restrict__ W2,
                         const float* __restrict__ Wh1) {
    int i = blockIdx.x * blockDim.x + threadIdx.x;
    float v; __nv_bfloat16* dh; __nv_bfloat16* dl; int o;
    if (i < W1SZ) {
        int l = i / (HD * HD), rem = i % (HD * HD);
        int row = rem / HD, col = rem % HD;
        v = W1[(size_t)l * HD * KE + (size_t)row * KE + col];
        dh = g_w1hi; dl = g_w1lo; o = i;
    } else if (i < W1SZ + W2SZ) {
        o = i - W1SZ;
        v = W2[o];
        dh = g_w2hi; dl = g_w2lo;
    } else if (i < W1SZ + W2SZ + WHSZ) {
        o = i - W1SZ - W2SZ;
        v = Wh1[o];
        dh = g_whhi; dl = g_whlo;
    } else return;
    __nv_bfloat16 h = __float2bfloat16_rn(v);
    dh[o] = h;
    dl[o] = __float2bfloat16_rn(v - __bfloat162float(h));
}

// ---------------- init ----------------
__global__ void k_init(const int* __restrict__ gate, const float* __restrict__ emb, int n) {
    int idx = blockIdx.x * blockDim.x + threadIdx.x;
    if (idx >= n * HD) return;
    int v = idx / HD, f = idx % HD;
    float x = emb[gate[v] * HD + f];
    __nv_bfloat16 h = __float2bfloat16_rn(x);
    g_ahi[idx] = h;
    g_alo[idx] = __float2bfloat16_rn(x - __bfloat162float(h));
    if (f == 0) g_inv[v] = 1.0f / fmaxf((float)g_deg[v], 1.0f);
}

// ---------------- warp-MMA helpers ----------------
__device__ __forceinline__ uint32_t s2u(const void* p) {
    return (uint32_t)__cvta_generic_to_shared(p);
}
__device__ __forceinline__ void ldsm4(uint32_t* r, uint32_t addr) {
    asm volatile("ldmatrix.sync.aligned.m8n8.x4.shared.b16 {%0,%1,%2,%3}, [%4];"
        : "=r"(r[0]), "=r"(r[1]), "=r"(r[2]), "=r"(r[3]) : "r"(addr));
}
__device__ __forceinline__ void mma16816(float* d, const uint32_t* a, const uint32_t* b) {
    asm volatile("mma.sync.aligned.m16n8k16.row.col.f32.bf16.bf16.f32 "
        "{%0,%1,%2,%3}, {%4,%5,%6,%7}, {%8,%9}, {%0,%1,%2,%3};"
        : "+f"(d[0]), "+f"(d[1]), "+f"(d[2]), "+f"(d[3])
        : "r"(a[0]), "r"(a[1]), "r"(a[2]), "r"(a[3]), "r"(b[0]), "r"(b[1]));
}
__device__ __forceinline__ void cpa16(uint32_t d, const void* s) {
    asm volatile("cp.async.ca.shared.global [%0], [%1], 16;" :: "r"(d), "l"(s));
}
#define CP_COMMIT() asm volatile("cp.async.commit_group;" ::: "memory")

// ---------------- bf16x3 MMA GEMM, 512 threads, BK=64, double-buffered ----------------
// 16 warps, warp grid 4(m) x 4(n), warp tile 32x32 (mf=2, nf=4).
// BK=64 halves chunk count (8 for K=512) -> half the syncthreads/wait bubbles.
#define PITCH 72        // 64 bf16 + 8 pad; 144B rows, ldsm conflict-free
#define TSZ   18432     // one 128x72 bf16 tile
#define STG   73728     // 4 tiles per stage
__global__ __launch_bounds__(512) void k_gemm_mma(
    const __nv_bfloat16* __restrict__ A0h, const __nv_bfloat16* __restrict__ A0l,
    const __nv_bfloat16* __restrict__ A1h, const __nv_bfloat16* __restrict__ A1l,
    const __nv_bfloat16* __restrict__ Bh,  const __nv_bfloat16* __restrict__ Bl,
    const float* __restrict__ bias,
    float* __restrict__ outf, __nv_bfloat16* __restrict__ outhi, __nv_bfloat16* __restrict__ outlo,
    int K, int ws, int M, int act)
{
    extern __shared__ char smem[];
    const uint32_t us = s2u(smem);

    const int tid  = threadIdx.x;
    const int lane = tid & 31;
    const int wid  = tid >> 5;
    const int r0   = blockIdx.x * 128;
    const int nb0  = blockIdx.y * 128;
    const int m0w  = (wid >> 2) * 32;
    const int n0w  = (wid & 3) * 32;

    float acc[2][4][4];
#pragma unroll
    for (int i = 0; i < 2; i++)
#pragma unroll
        for (int j = 0; j < 4; j++)
#pragma unroll
            for (int t = 0; t < 4; t++) acc[i][j][t] = 0.f;

    const int nch = K >> 6;           // BK=64 chunks
    const int lr  = tid >> 2;         // 0..127 row
    const int lcb = (tid & 3) * 8;    // col granule base (bf16)

    auto load_chunk = [&](int ch, int stage) {
        const int kc = ch << 6;
        const __nv_bfloat16* Ah = (kc < HD) ? A0h : A1h;
        const __nv_bfloat16* Al = (kc < HD) ? A0l : A1l;
        const int acol = (kc < HD) ? kc : (kc - HD);
        const uint32_t base = us + stage * STG;
        int g = r0 + lr; if (g >= M) g = M - 1;
#pragma unroll
        for (int gi = 0; gi < 2; gi++) {
            int c = lcb + gi * 32;
            uint32_t so = (uint32_t)(lr * PITCH + c) * 2;
            cpa16(base + so,           &Ah[(size_t)g * HD + acol + c]);
            cpa16(base + TSZ + so,     &Al[(size_t)g * HD + acol + c]);
            cpa16(base + 2 * TSZ + so, &Bh[(size_t)(nb0 + lr) * ws + kc + c]);
            cpa16(base + 3 * TSZ + so, &Bl[(size_t)(nb0 + lr) * ws + kc + c]);
        }
    };

    load_chunk(0, 0);
    CP_COMMIT();

    for (int ch = 0; ch < nch; ch++) {
        if (ch + 1 < nch) {
            load_chunk(ch + 1, (ch + 1) & 1);
            CP_COMMIT();
            asm volatile("cp.async.wait_group 1;" ::: "memory");
        } else {
            asm volatile("cp.async.wait_group 0;" ::: "memory");
        }
        __syncthreads();

        const uint32_t base = us + (ch & 1) * STG;
        const uint32_t uA = base, uAl = base + TSZ, uB = base + 2 * TSZ, uBl = base + 3 * TSZ;
#pragma unroll
        for (int ks = 0; ks < 4; ks++) {
            const int kk = ks * 16;
            uint32_t ah[2][4], al[2][4];
            {
                int ar = (lane & 7) + ((lane >> 3) & 1) * 8;
                int ac = kk + ((lane >> 4) & 1) * 8;
#pragma unroll
                for (int mf = 0; mf < 2; mf++) {
                    uint32_t off = (uint32_t)((m0w + mf * 16 + ar) * PITCH + ac) * 2;
                    ldsm4(ah[mf], uA + off);
                    ldsm4(al[mf], uAl + off);
                }
            }
            uint32_t bh[2][4], bl[2][4];
            {
                int br = ((lane >> 4) & 1) * 8 + (lane & 7);
                int bc = kk + ((lane >> 3) & 1) * 8;
#pragma unroll
                for (int nb2 = 0; nb2 < 2; nb2++) {
                    uint32_t off = (uint32_t)((n0w + nb2 * 16 + br) * PITCH + bc) * 2;
                    ldsm4(bh[nb2], uB + off);
                    ldsm4(bl[nb2], uBl + off);
                }
            }
#pragma unroll
            for (int mf = 0; mf < 2; mf++)
#pragma unroll
                for (int nf = 0; nf < 4; nf++) {
                    const uint32_t* B0 = &bh[nf >> 1][(nf & 1) * 2];
                    const uint32_t* B1 = &bl[nf >> 1][(nf & 1) * 2];
                    mma16816(acc[mf][nf], ah[mf], B0);
                    mma16816(acc[mf][nf], al[mf], B0);
                    mma16816(acc[mf][nf], ah[mf], B1);
                }
        }
        __syncthreads();
    }

    // epilogue
    const int rq = lane >> 2, cq = (lane & 3) * 2;
#pragma unroll
    for (int mf = 0; mf < 2; mf++) {
#pragma unroll
        for (int nf = 0; nf < 4; nf++) {
            int col = nb0 + n0w + nf * 8 + cq;
            float b0 = 0.f, b1 = 0.f;
            if (bias) { b0 = __ldg(&bias[col]); b1 = __ldg(&bias[col + 1]); }
            int row0 = r0 + m0w + mf * 16 + rq;
#pragma unroll
            for (int half = 0; half < 2; half++) {
                int row = row0 + half * 8;
                if (row < M) {
                    float ox = acc[mf][nf][half * 2 + 0] + b0;
                    float oy = acc[mf][nf][half * 2 + 1] + b1;
                    if (act) { ox = fmaxf(ox, 0.f); oy = fmaxf(oy, 0.f); }
                    size_t idx = (size_t)row * HD + col;
                    if (outf) *(float2*)&outf[idx] = make_float2(ox, oy);
                    if (outhi) {
                        __nv_bfloat16 h0 = __float2bfloat16_rn(ox);
                        __nv_bfloat16 h1 = __float2bfloat16_rn(oy);
                        *(__nv_bfloat162*)&outhi[idx] = {h0, h1};
                        *(__nv_bfloat162*)&outlo[idx] =
                            {__float2bfloat16_rn(ox - __bfloat162float(h0)),
                             __float2bfloat16_rn(oy - __bfloat162float(h1))};
                    }
                }
            }
        }
    }
}

// ---------------- fused edge + segmented mean: warp-per-node ----------------
#define ESEG_BLOCKS 1563
__global__ __launch_bounds__(256) void k_edge_seg(
    const float* __restrict__ z, const int* __restrict__ src,
    const float* __restrict__ w, const float* __restrict__ W1l, int n)
{
    __shared__ float sc[3][HD];
    const int tid  = threadIdx.x;
    const int lane = tid & 31;
    const int wloc = tid >> 5;

    if (tid < HD) {
        sc[0][tid] = W1l[(size_t)tid * KE + HD + 0];
        sc[1][tid] = W1l[(size_t)tid * KE + HD + 1];
        sc[2][tid] = W1l[(size_t)tid * KE + HD + 2];
    }
    __syncthreads();

    const int f0 = lane * 8;
    float c0[8], c1[8], c2[8];
#pragma unroll
    for (int j = 0; j < 8; j++) {
        c0[j] = sc[0][f0 + j];
        c1[j] = sc[1][f0 + j];
        c2[j] = sc[2][f0 + j];
    }

    const int gwarp  = blockIdx.x * 8 + wloc;
    const int nwarps = ESEG_BLOCKS * 8;

    for (int v = gwarp; v < n; v += nwarps) {
        const int lo = g_rowptr[v], hi = g_rowptr[v + 1];
        float a[8];
#pragma unroll
        for (int j = 0; j < 8; j++) a[j] = 0.f;

        for (int i = lo; i < hi; i++) {
            int e = __ldg(&g_esorted[i]);
            int s = __ldg(&src[e]);
            float w0 = __ldg(&w[(size_t)e * 3 + 0]);
            float w1 = __ldg(&w[(size_t)e * 3 + 1]);
            float w2 = __ldg(&w[(size_t)e * 3 + 2]);
            const float4* zr = (const float4*)&z[(size_t)s * HD];
            float4 za = __ldg(&zr[lane * 2 + 0]);
            float4 zb = __ldg(&zr[lane * 2 + 1]);
            float t[8];
            t[0] = za.x; t[1] = za.y; t[2] = za.z; t[3] = za.w;
            t[4] = zb.x; t[5] = zb.y; t[6] = zb.z; t[7] = zb.w;
#pragma unroll
            for (int j = 0; j < 8; j++) {
                float val = t[j] + c0[j] * w0 + c1[j] * w1 + c2[j] * w2;
                a[j] += (val > 0.f) ? val : 0.01f * val;
            }
        }
        const float inv = g_inv[v];
        uint32_t hpack[4], lpack[4];
#pragma unroll
        for (int j = 0; j < 4; j++) {
            float r0v = a[j * 2 + 0] * inv;
            float r1v = a[j * 2 + 1] * inv;
            __nv_bfloat16 h0 = __float2bfloat16_rn(r0v);
            __nv_bfloat16 h1 = __float2bfloat16_rn(r1v);
            __nv_bfloat162 hp = {h0, h1};
            __nv_bfloat162 lp = {__float2bfloat16_rn(r0v - __bfloat162float(h0)),
                                 __float2bfloat16_rn(r1v - __bfloat162float(h1))};
            hpack[j] = *(uint32_t*)&hp;
            lpack[j] = *(uint32_t*)&lp;
        }
        size_t idx = (size_t)v * HD + f0;
        *(uint4*)&g_nhi[idx] = *(uint4*)hpack;
        *(uint4*)&g_nlo[idx] = *(uint4*)lpack;
    }
}

// ---------------- head ----------------
__global__ void k_head2(const float* __restrict__ x, const float* __restrict__ Wh2,
                        const float* __restrict__ bh2, float* __restrict__ out, int n) {
    int gtid = blockIdx.x * blockDim.x + threadIdx.x;
    int v = gtid >> 5;
    int lane = gtid & 31;
    if (v >= n) return;
    float s = 0.f;
#pragma unroll
    for (int k = lane; k < HD; k += 32) s += x[(size_t)v * HD + k] * Wh2[k];
#pragma unroll
    for (int o = 16; o; o >>= 1) s += __shfl_xor_sync(0xffffffffu, s, o);
    if (lane == 0) out[v] = s + bh2[0];
}

// ---------------- host ----------------
extern "C" void kernel_launch(void* const* d_in, const int* in_sizes, int n_in,
                              void* d_out, int out_size) {
    const int*   gate = (const int*)  d_in[0];
    const int*   src  = (const int*)  d_in[1];
    const int*   dst  = (const int*)  d_in[2];
    const float* w    = (const float*)d_in[3];
    const float* emb  = (const float*)d_in[4];
    const float* W1   = (const float*)d_in[5];
    const float* W2   = (const float*)d_in[6];
    const float* b2   = (const float*)d_in[7];
    const float* Wh1  = (const float*)d_in[8];
    const float* bh1  = (const float*)d_in[9];
    const float* Wh2  = (const float*)d_in[10];
    const float* bh2  = (const float*)d_in[11];
    float* out = (float*)d_out;

    int n = in_sizes[0];
    int e = in_sizes[1];

    static int smem_set = 0;
    if (!smem_set) {
        cudaFuncSetAttribute(k_gemm_mma, cudaFuncAttributeMaxDynamicSharedMemorySize, 2 * STG);
        smem_set = 1;
    }

    void* p;
    cudaGetSymbolAddress(&p, g_ahi); __nv_bfloat16* ahi = (__nv_bfloat16*)p;
    cudaGetSymbolAddress(&p, g_alo); __nv_bfloat16* alo = (__nv_bfloat16*)p;
    cudaGetSymbolAddress(&p, g_bhi); __nv_bfloat16* bhi = (__nv_bfloat16*)p;
    cudaGetSymbolAddress(&p, g_blo); __nv_bfloat16* blo = (__nv_bfloat16*)p;
    cudaGetSymbolAddress(&p, g_nhi); __nv_bfloat16* nhi = (__nv_bfloat16*)p;
    cudaGetSymbolAddress(&p, g_nlo); __nv_bfloat16* nlo = (__nv_bfloat16*)p;
    cudaGetSymbolAddress(&p, g_z);   float* z = (float*)p;
    cudaGetSymbolAddress(&p, g_w1hi); __nv_bfloat16* w1hi = (__nv_bfloat16*)p;
    cudaGetSymbolAddress(&p, g_w1lo); __nv_bfloat16* w1lo = (__nv_bfloat16*)p;
    cudaGetSymbolAddress(&p, g_w2hi); __nv_bfloat16* w2hi = (__nv_bfloat16*)p;
    cudaGetSymbolAddress(&p, g_w2lo); __nv_bfloat16* w2lo = (__nv_bfloat16*)p;
    cudaGetSymbolAddress(&p, g_whhi); __nv_bfloat16* whhi = (__nv_bfloat16*)p;
    cudaGetSymbolAddress(&p, g_whlo); __nv_bfloat16* whlo = (__nv_bfloat16*)p;
    cudaGetSymbolAddress(&p, g_deg); int* degp = (int*)p;

    cudaMemsetAsync(degp, 0, (size_t)n * sizeof(int));
    k_deg    <<<(e + 255) / 256, 256>>>(dst, e);
    k_scan   <<<1, 1024>>>(n);
    k_scatter<<<(e + 255) / 256, 256>>>(dst, e);
    k_segsort<<<(n + 255) / 256, 256>>>(n);
    k_wsplit <<<(W1SZ + W2SZ + WHSZ + 255) / 256, 256>>>(W1, W2, Wh1);
    k_init   <<<((size_t)n * HD + 255) / 256, 256>>>(gate, emb, n);

    __nv_bfloat16 *pah = ahi, *pal = alo, *pbh = bhi, *pbl = blo;
    dim3 gg((n + 127) / 128, 2);
    for (int l = 0; l < NL; l++) {
        const float* W1l = W1 + (size_t)l * HD * KE;
        k_gemm_mma<<<gg, 512, 2 * STG>>>(pah, pal, pah, pal,
                                         w1hi + (size_t)l * HD * HD, w1lo + (size_t)l * HD * HD,
                                         nullptr, z, nullptr, nullptr, HD, HD, n, 0);
        k_edge_seg<<<ESEG_BLOCKS, 256>>>(z, src, w, W1l, n);
        k_gemm_mma<<<gg, 512, 2 * STG>>>(pah, pal, nhi, nlo,
                                         w2hi + (size_t)l * HD * 512, w2lo + (size_t)l * HD * 512,
                                         b2 + (size_t)l * HD, nullptr, pbh, pbl, 512, 512, n, 1);
        __nv_bfloat16* t;
        t = pah; pah = pbh; pbh = t;
        t = pal; pal = pbl; pbl = t;
    }
    k_gemm_mma<<<gg, 512, 2 * STG>>>(pah, pal, pah, pal, whhi, whlo,
                                     bh1, z, nullptr, nullptr, HD, HD, n, 1);
    k_head2<<<((size_t)n * 32 + 255) / 256, 256>>>(z, Wh2, bh2, out, n);
}